// round 6
// baseline (speedup 1.0000x reference)
#include <cuda_runtime.h>
#include <cuda_bf16.h>
#include <math.h>
#include <stdint.h>

// ---------------- problem constants ----------------
#define BB 1024
#define TT 128
#define FF 128
#define HH 512
#define G4 2048            // 4*HH
#define KC 768             // 2*FF + HH
#define BTn (BB*TT)        // 131072
#define GRID 148           // persistent kernel: one block per SM, all co-resident

constexpr size_t BTFc    = (size_t)BTn * FF;
constexpr size_t OFF_IMP = 0;
constexpr size_t OFF_CH1 = BTFc;
constexpr size_t OFF_HT  = 2 * BTFc;
constexpr size_t OFF_XH  = 2 * BTFc + (size_t)BB * HH;
constexpr size_t OFF_CH2 = OFF_XH + BTFc;
constexpr size_t OFF_ZH  = OFF_CH2 + BTFc;

// ---------------- device scratch (static, no allocs) ----------------
__device__ __align__(16) float g_gamma_x[(size_t)BTn * FF];   // 64 MB
__device__ __align__(16) float g_gamma_h[(size_t)BTn * HH];   // 256 MB
__device__ __align__(16) float g_alpha  [(size_t)BTn * FF];   // 64 MB
__device__ __align__(16) float g_h [BB * HH];
__device__ __align__(16) float g_c [BB * HH];
__device__ __align__(16) float g_cc[BB * FF];
__device__ __align__(16) float g_bcat[G4];                    // gate-interleaved

// bf16 split, TRANSPOSED weights: layout [K][N] row-major
__device__ __align__(16) __nv_bfloat16 g_WghH  [FF * HH],   g_WghL  [FF * HH];    // K=128,N=512
__device__ __align__(16) __nv_bfloat16 g_WcombH[256 * FF],  g_WcombL[256 * FF];   // K=256,N=128
__device__ __align__(16) __nv_bfloat16 g_WhistH[HH * FF],   g_WhistL[HH * FF];    // K=512,N=128
__device__ __align__(16) __nv_bfloat16 g_WodH  [FF * FF],   g_WodL  [FF * FF];    // K=128,N=128
__device__ __align__(16) __nv_bfloat16 g_WcatH[(size_t)KC * G4], g_WcatL[(size_t)KC * G4]; // K=768,N=2048 interleaved

// grid barrier state (self-restoring across graph replays)
__device__ unsigned g_bar_cnt = 0;
__device__ unsigned g_bar_gen = 0;

__device__ __forceinline__ float sigm(float x) { return 1.0f / (1.0f + expf(-x)); }

__device__ __forceinline__ void split_w(__nv_bfloat16* H, __nv_bfloat16* L, size_t i, float w) {
    __nv_bfloat16 h = __float2bfloat16(w);
    H[i] = h;
    L[i] = __float2bfloat16(w - __bfloat162float(h));
}

__device__ __forceinline__ void gbar() {
    __syncthreads();
    if (threadIdx.x == 0) {
        __threadfence();
        unsigned g = *(volatile unsigned*)&g_bar_gen;
        unsigned arr = atomicAdd(&g_bar_cnt, 1);
        if (arr == GRID - 1) {
            g_bar_cnt = 0;
            __threadfence();
            atomicExch(&g_bar_gen, g + 1);
        } else {
            while (*(volatile unsigned*)&g_bar_gen == g) { __nanosleep(32); }
            __threadfence();
        }
    }
    __syncthreads();
}

// ---------------- precompute ----------------
__global__ void k_prep(const float* __restrict__ D,    const float* __restrict__ Wgx,
                       const float* __restrict__ bgx,  const float* __restrict__ Wfeat,
                       const float* __restrict__ Wih,  const float* __restrict__ Whh,
                       const float* __restrict__ bih,  const float* __restrict__ bhh,
                       const float* __restrict__ Wgh,  const float* __restrict__ Wcomb,
                       const float* __restrict__ Whist)
{
    size_t tid    = (size_t)blockIdx.x * blockDim.x + threadIdx.x;
    size_t stride = (size_t)gridDim.x * blockDim.x;

    for (size_t i = tid; i < (size_t)BTn * FF; i += stride) {
        int f = (int)(i & (FF - 1));
        float v = D[i] * Wgx[f * FF + f] + bgx[f];
        g_gamma_x[i] = expf(-fmaxf(v, 0.0f));
    }
    // gate-interleaved bias: col n' = j*4+g  <->  orig n = g*512+j
    for (size_t i = tid; i < (size_t)G4; i += stride) {
        int j = (int)(i >> 2), g = (int)(i & 3), n = g * HH + j;
        g_bcat[i] = bih[n] + bhh[n];
    }
    for (size_t i = tid; i < (size_t)BB * HH; i += stride) { g_h[i] = 0.0f; g_c[i] = 0.0f; }

    for (size_t i = tid; i < (size_t)FF * HH; i += stride) {     // W_gh^T
        int k = (int)(i / HH), n = (int)(i % HH);
        split_w(g_WghH, g_WghL, i, Wgh[(size_t)n * FF + k]);
    }
    for (size_t i = tid; i < (size_t)256 * FF; i += stride) {    // W_comb^T
        int k = (int)(i / FF), n = (int)(i % FF);
        split_w(g_WcombH, g_WcombL, i, Wcomb[(size_t)n * 256 + k]);
    }
    for (size_t i = tid; i < (size_t)HH * FF; i += stride) {     // W_hist^T
        int k = (int)(i / FF), n = (int)(i % FF);
        split_w(g_WhistH, g_WhistL, i, Whist[(size_t)n * HH + k]);
    }
    for (size_t i = tid; i < (size_t)FF * FF; i += stride) {     // W_feat^T off-diag
        int k = (int)(i / FF), n = (int)(i % FF);
        float w = (k == n) ? 0.0f : Wfeat[(size_t)n * FF + k];
        split_w(g_WodH, g_WodL, i, w);
    }
    // W_cat^T, gate-interleaved columns
    for (size_t i = tid; i < (size_t)KC * G4; i += stride) {
        int k = (int)(i / G4), np = (int)(i % G4);
        int j = np >> 2, g = np & 3, n = g * HH + j;
        float w = (k < 2 * FF) ? Wih[(size_t)n * (2 * FF) + k]
                               : Whh[(size_t)n * HH + (k - 2 * FF)];
        split_w(g_WcatH, g_WcatL, i, w);
    }
}

// ---------------- mma helpers ----------------
__device__ __forceinline__ void ldmA(uint32_t* r, const __nv_bfloat16* p) {
    uint32_t a = (uint32_t)__cvta_generic_to_shared(p);
    asm volatile("ldmatrix.sync.aligned.m8n8.x4.shared.b16 {%0,%1,%2,%3}, [%4];"
                 : "=r"(r[0]), "=r"(r[1]), "=r"(r[2]), "=r"(r[3]) : "r"(a));
}
__device__ __forceinline__ void ldmBT(uint32_t* r, const __nv_bfloat16* p) {
    uint32_t a = (uint32_t)__cvta_generic_to_shared(p);
    asm volatile("ldmatrix.sync.aligned.m8n8.x4.trans.shared.b16 {%0,%1,%2,%3}, [%4];"
                 : "=r"(r[0]), "=r"(r[1]), "=r"(r[2]), "=r"(r[3]) : "r"(a));
}
__device__ __forceinline__ void mma16816(float* d, const uint32_t* a, const uint32_t* b) {
    asm volatile("mma.sync.aligned.m16n8k16.row.col.f32.bf16.bf16.f32 "
                 "{%0,%1,%2,%3}, {%4,%5,%6,%7}, {%8,%9}, {%0,%1,%2,%3};"
                 : "+f"(d[0]), "+f"(d[1]), "+f"(d[2]), "+f"(d[3])
                 : "r"(a[0]), "r"(a[1]), "r"(a[2]), "r"(a[3]), "r"(b[0]), "r"(b[1]));
}
__device__ __forceinline__ void splitA_store(__nv_bfloat16* pH, __nv_bfloat16* pL, float4 a) {
    __nv_bfloat16 h0 = __float2bfloat16(a.x), h1 = __float2bfloat16(a.y);
    __nv_bfloat16 h2 = __float2bfloat16(a.z), h3 = __float2bfloat16(a.w);
    __nv_bfloat16 l0 = __float2bfloat16(a.x - __bfloat162float(h0));
    __nv_bfloat16 l1 = __float2bfloat16(a.y - __bfloat162float(h1));
    __nv_bfloat16 l2 = __float2bfloat16(a.z - __bfloat162float(h2));
    __nv_bfloat16 l3 = __float2bfloat16(a.w - __bfloat162float(h3));
    ((__nv_bfloat162*)pH)[0] = __halves2bfloat162(h0, h1);
    ((__nv_bfloat162*)pH)[1] = __halves2bfloat162(h2, h3);
    ((__nv_bfloat162*)pL)[0] = __halves2bfloat162(l0, l1);
    ((__nv_bfloat162*)pL)[1] = __halves2bfloat162(l2, l3);
}
__device__ __forceinline__ void split_scalar(__nv_bfloat16* pH, __nv_bfloat16* pL, float v) {
    __nv_bfloat16 h = __float2bfloat16(v);
    *pH = h;
    *pL = __float2bfloat16(v - __bfloat162float(h));
}

// ============================================================================
// Precompute GEMMs (parallel over all B*T rows): GH and ALPHA
// ============================================================================
enum Mode { M_GH = 0, M_ALPHA = 1 };

template <int MODE>
__device__ __forceinline__ float4 loadApre(int row, int k, const float* __restrict__ Mm,
                                           const float* __restrict__ D)
{
    if (MODE == M_GH) {
        return *(const float4*)(D + (size_t)row * FF + k);
    } else {
        if (k < FF) return *(const float4*)(g_gamma_x + (size_t)row * FF + k);
        return *(const float4*)(Mm + (size_t)row * FF + (k - FF));
    }
}

template <int MODE>
__global__ __launch_bounds__(256)
void k_mma(const float* __restrict__ Mm, const float* __restrict__ D,
           const float* __restrict__ bias)
{
    constexpr int KD = (MODE == M_GH) ? FF : 2 * FF;
    constexpr int ND = (MODE == M_GH) ? HH : FF;
    constexpr int BM = 64, BN = 128;
    constexpr int LDA = 40, LDB = BN + 8;

    const __nv_bfloat16* WH = (MODE == M_GH) ? g_WghH : g_WcombH;
    const __nv_bfloat16* WL = (MODE == M_GH) ? g_WghL : g_WcombL;

    __shared__ __align__(16) __nv_bfloat16 AsH[BM * LDA], AsL[BM * LDA];
    __shared__ __align__(16) __nv_bfloat16 BsH[32 * LDB], BsL[32 * LDB];

    const int tid = threadIdx.x, lane = tid & 31, w = tid >> 5;
    const int wm = w >> 2, wn = w & 3;                 // 2x4 warps, warp tile 32x32
    const int m0 = blockIdx.x * BM, n0 = blockIdx.y * BN;
    const int mA = tid >> 2, kA = (tid & 3) * 4;
    const int lr = lane & 15, lc = (lane >> 4) * 8;

    float acc[2][4][4];
    #pragma unroll
    for (int i = 0; i < 2; i++) for (int nb = 0; nb < 4; nb++) for (int e = 0; e < 4; e++)
        acc[i][nb][e] = 0.0f;

    for (int kt = 0; kt < KD; kt += 32) {
        float4 a1 = loadApre<MODE>(m0 + mA, kt + kA,      Mm, D);
        float4 a2 = loadApre<MODE>(m0 + mA, kt + kA + 16, Mm, D);
        uint4 bqh[2], bql[2];
        #pragma unroll
        for (int q = 0; q < 2; q++) {
            int cidx = q * 256 + tid;
            int row = cidx >> 4, col = (cidx & 15) * 8;
            size_t gi = (size_t)(kt + row) * ND + n0 + col;
            bqh[q] = *(const uint4*)(WH + gi);
            bql[q] = *(const uint4*)(WL + gi);
        }
        __syncthreads();
        splitA_store(&AsH[mA * LDA + kA],      &AsL[mA * LDA + kA],      a1);
        splitA_store(&AsH[mA * LDA + kA + 16], &AsL[mA * LDA + kA + 16], a2);
        #pragma unroll
        for (int q = 0; q < 2; q++) {
            int cidx = q * 256 + tid;
            int row = cidx >> 4, col = (cidx & 15) * 8;
            *(uint4*)&BsH[row * LDB + col] = bqh[q];
            *(uint4*)&BsL[row * LDB + col] = bql[q];
        }
        __syncthreads();
        #pragma unroll
        for (int kk = 0; kk < 32; kk += 16) {
            uint32_t ah[2][4], al[2][4];
            #pragma unroll
            for (int i = 0; i < 2; i++) {
                const int rowb = wm * 32 + i * 16 + lr;
                ldmA(ah[i], &AsH[rowb * LDA + kk + lc]);
                ldmA(al[i], &AsL[rowb * LDA + kk + lc]);
            }
            uint32_t bh[4][2], bl[4][2];
            #pragma unroll
            for (int g = 0; g < 2; g++) {
                uint32_t r4[4];
                const int coff = wn * 32 + g * 16 + lc;
                ldmBT(r4, &BsH[(kk + lr) * LDB + coff]);
                bh[2*g][0] = r4[0]; bh[2*g][1] = r4[1];
                bh[2*g+1][0] = r4[2]; bh[2*g+1][1] = r4[3];
                ldmBT(r4, &BsL[(kk + lr) * LDB + coff]);
                bl[2*g][0] = r4[0]; bl[2*g][1] = r4[1];
                bl[2*g+1][0] = r4[2]; bl[2*g+1][1] = r4[3];
            }
            #pragma unroll
            for (int i = 0; i < 2; i++)
                #pragma unroll
                for (int nb = 0; nb < 4; nb++) {
                    mma16816(acc[i][nb], ah[i], bh[nb]);
                    mma16816(acc[i][nb], al[i], bh[nb]);
                    mma16816(acc[i][nb], ah[i], bl[nb]);
                }
        }
    }
    #pragma unroll
    for (int i = 0; i < 2; i++)
        #pragma unroll
        for (int nb = 0; nb < 4; nb++) {
            const int rbase = m0 + wm * 32 + i * 16 + (lane >> 2);
            const int cbase = n0 + wn * 32 + nb * 8 + (lane & 3) * 2;
            #pragma unroll
            for (int e = 0; e < 4; e++) {
                const int r = rbase + (e >> 1) * 8;
                const int c = cbase + (e & 1);
                float v = acc[i][nb][e] + bias[c];
                if (MODE == M_GH) g_gamma_h[(size_t)r * HH + c] = expf(-fmaxf(v, 0.0f));
                else              g_alpha  [(size_t)r * FF + c] = sigm(v);
            }
        }
}

// ============================================================================
// Persistent scan kernel
// ============================================================================
// Phase A smem layout (BM=32, BN=128):
//   AsH 0 (2560) AsL 2560 | BsH 5120 (8704) BsL 13824 | xcH 22528 (8704) xcL 31232 | xh 39936 (16384) -> 56320
// Phase B smem layout (BM=64, BN=256):
//   AsH 0 (5120) AsL 5120 | BsH 10240 (16896) BsL 27136 -> 44032 ; sg overlays [0,66560) post-sync
#define SMEM_BYTES 66560

__device__ __forceinline__ void phaseA(int tile, int t,
    const float* __restrict__ X, const float* __restrict__ Mm,
    const float* __restrict__ bh_, const float* __restrict__ bf_,
    float* __restrict__ outp, char* sm)
{
    __nv_bfloat16* AsH = (__nv_bfloat16*)(sm);
    __nv_bfloat16* AsL = (__nv_bfloat16*)(sm + 2560);
    __nv_bfloat16* BsH = (__nv_bfloat16*)(sm + 5120);
    __nv_bfloat16* BsL = (__nv_bfloat16*)(sm + 13824);
    __nv_bfloat16* xcH = (__nv_bfloat16*)(sm + 22528);
    __nv_bfloat16* xcL = (__nv_bfloat16*)(sm + 31232);
    float*         xhS = (float*)(sm + 39936);
    constexpr int LDA = 40, LDB = 136, LDX = 136;

    const int tid = threadIdx.x, lane = tid & 31, w = tid >> 5;
    const int wm = w >> 2, wn = w & 3;                 // 2x4 warps, warp tile 16x32
    const int m0 = tile * 32;
    const int arow = tid >> 3, akq = (tid & 7) * 4;    // A: 32 rows x 32 k
    const int lr = lane & 15, lc = (lane >> 4) * 8;

    // ---- XH: x_h = (h .* gamma_h) @ Whist^T, K=512 ----
    float acc[4][4];
    #pragma unroll
    for (int nb = 0; nb < 4; nb++) for (int e = 0; e < 4; e++) acc[nb][e] = 0.0f;

    for (int kt = 0; kt < HH; kt += 32) {
        const int gr = m0 + arow, k = kt + akq;
        float4 h4 = *(const float4*)(g_h + (size_t)gr * HH + k);
        float4 gg = *(const float4*)(g_gamma_h + ((size_t)gr * TT + t) * HH + k);
        float4 a  = make_float4(h4.x * gg.x, h4.y * gg.y, h4.z * gg.z, h4.w * gg.w);
        uint4 bqh[2], bql[2];
        #pragma unroll
        for (int q = 0; q < 2; q++) {
            int cidx = q * 256 + tid;
            int row = cidx >> 4, col = (cidx & 15) * 8;
            size_t gi = (size_t)(kt + row) * FF + col;
            bqh[q] = *(const uint4*)(g_WhistH + gi);
            bql[q] = *(const uint4*)(g_WhistL + gi);
        }
        __syncthreads();
        splitA_store(&AsH[arow * LDA + akq], &AsL[arow * LDA + akq], a);
        #pragma unroll
        for (int q = 0; q < 2; q++) {
            int cidx = q * 256 + tid;
            int row = cidx >> 4, col = (cidx & 15) * 8;
            *(uint4*)&BsH[row * LDB + col] = bqh[q];
            *(uint4*)&BsL[row * LDB + col] = bql[q];
        }
        __syncthreads();
        #pragma unroll
        for (int kk = 0; kk < 32; kk += 16) {
            uint32_t ah[4], al[4];
            const int rowb = wm * 16 + lr;
            ldmA(ah, &AsH[rowb * LDA + kk + lc]);
            ldmA(al, &AsL[rowb * LDA + kk + lc]);
            uint32_t bhf[4][2], blf[4][2];
            #pragma unroll
            for (int g = 0; g < 2; g++) {
                uint32_t r4[4];
                const int coff = wn * 32 + g * 16 + lc;
                ldmBT(r4, &BsH[(kk + lr) * LDB + coff]);
                bhf[2*g][0] = r4[0]; bhf[2*g][1] = r4[1];
                bhf[2*g+1][0] = r4[2]; bhf[2*g+1][1] = r4[3];
                ldmBT(r4, &BsL[(kk + lr) * LDB + coff]);
                blf[2*g][0] = r4[0]; blf[2*g][1] = r4[1];
                blf[2*g+1][0] = r4[2]; blf[2*g+1][1] = r4[3];
            }
            #pragma unroll
            for (int nb = 0; nb < 4; nb++) {
                mma16816(acc[nb], ah, bhf[nb]);
                mma16816(acc[nb], al, bhf[nb]);
                mma16816(acc[nb], ah, blf[nb]);
            }
        }
    }

    // XH epilogue -> xh smem (fp32), xc smem (bf16 split), outp XH
    #pragma unroll
    for (int nb = 0; nb < 4; nb++) {
        const int rl0 = wm * 16 + (lane >> 2);
        const int c0  = wn * 32 + nb * 8 + (lane & 3) * 2;
        #pragma unroll
        for (int e = 0; e < 4; e++) {
            const int rl = rl0 + (e >> 1) * 8;
            const int c  = c0 + (e & 1);
            const int r  = m0 + rl;
            float v = acc[nb][e] + bh_[c];
            size_t idx = ((size_t)r * TT + t) * FF + c;
            outp[OFF_XH + idx] = v;
            xhS[rl * FF + c] = v;
            float mm = Mm[idx], xx = X[idx];
            float xc = mm * xx + (1.0f - mm) * v;
            split_scalar(&xcH[rl * LDX + c], &xcL[rl * LDX + c], xc);
        }
    }

    // ---- ZH: z_h = x_c @ Wod^T, K=128 (A from smem) ----
    float accz[4][4];
    #pragma unroll
    for (int nb = 0; nb < 4; nb++) for (int e = 0; e < 4; e++) accz[nb][e] = 0.0f;

    for (int kt = 0; kt < FF; kt += 32) {
        uint4 bqh[2], bql[2];
        #pragma unroll
        for (int q = 0; q < 2; q++) {
            int cidx = q * 256 + tid;
            int row = cidx >> 4, col = (cidx & 15) * 8;
            size_t gi = (size_t)(kt + row) * FF + col;
            bqh[q] = *(const uint4*)(g_WodH + gi);
            bql[q] = *(const uint4*)(g_WodL + gi);
        }
        __syncthreads();   // also covers xc writes before first ldmA
        #pragma unroll
        for (int q = 0; q < 2; q++) {
            int cidx = q * 256 + tid;
            int row = cidx >> 4, col = (cidx & 15) * 8;
            *(uint4*)&BsH[row * LDB + col] = bqh[q];
            *(uint4*)&BsL[row * LDB + col] = bql[q];
        }
        __syncthreads();
        #pragma unroll
        for (int kk = 0; kk < 32; kk += 16) {
            uint32_t ah[4], al[4];
            const int rowb = wm * 16 + lr;
            ldmA(ah, &xcH[rowb * LDX + kt + kk + lc]);
            ldmA(al, &xcL[rowb * LDX + kt + kk + lc]);
            uint32_t bhf[4][2], blf[4][2];
            #pragma unroll
            for (int g = 0; g < 2; g++) {
                uint32_t r4[4];
                const int coff = wn * 32 + g * 16 + lc;
                ldmBT(r4, &BsH[(kk + lr) * LDB + coff]);
                bhf[2*g][0] = r4[0]; bhf[2*g][1] = r4[1];
                bhf[2*g+1][0] = r4[2]; bhf[2*g+1][1] = r4[3];
                ldmBT(r4, &BsL[(kk + lr) * LDB + coff]);
                blf[2*g][0] = r4[0]; blf[2*g][1] = r4[1];
                blf[2*g+1][0] = r4[2]; blf[2*g+1][1] = r4[3];
            }
            #pragma unroll
            for (int nb = 0; nb < 4; nb++) {
                mma16816(accz[nb], ah, bhf[nb]);
                mma16816(accz[nb], al, bhf[nb]);
                mma16816(accz[nb], ah, blf[nb]);
            }
        }
    }

    // ZH epilogue: c_h / c_c / imputed, write outputs + g_cc
    #pragma unroll
    for (int nb = 0; nb < 4; nb++) {
        const int rl0 = wm * 16 + (lane >> 2);
        const int c0  = wn * 32 + nb * 8 + (lane & 3) * 2;
        #pragma unroll
        for (int e = 0; e < 4; e++) {
            const int rl = rl0 + (e >> 1) * 8;
            const int c  = c0 + (e & 1);
            const int r  = m0 + rl;
            float v = accz[nb][e] + bf_[c];
            size_t idx = ((size_t)r * TT + t) * FF + c;
            float al2 = g_alpha[idx];
            float xh  = xhS[rl * FF + c];
            float ch  = al2 * v + (1.0f - al2) * xh;
            float mm  = Mm[idx], xx = X[idx];
            float cc  = mm * xx + (1.0f - mm) * ch;
            outp[OFF_ZH  + idx] = v;
            outp[OFF_CH1 + idx] = ch;
            outp[OFF_CH2 + idx] = ch;
            outp[OFF_IMP + idx] = cc;
            g_cc[(size_t)r * FF + c] = cc;
        }
    }
}

__device__ __forceinline__ float4 loadGatesA(int row, int k, int t, const float* __restrict__ Mm)
{
    if (k < FF)     return *(const float4*)(g_cc + (size_t)row * FF + k);
    if (k < 2 * FF) return *(const float4*)(Mm + ((size_t)row * TT + t) * FF + (k - FF));
    int kh = k - 2 * FF;
    float4 h = *(const float4*)(g_h + (size_t)row * HH + kh);
    float4 g = *(const float4*)(g_gamma_h + ((size_t)row * TT + t) * HH + kh);
    return make_float4(h.x * g.x, h.y * g.y, h.z * g.z, h.w * g.w);
}

__device__ __forceinline__ void phaseB(int tile, int t, const float* __restrict__ Mm, char* sm)
{
    __nv_bfloat16* AsH = (__nv_bfloat16*)(sm);
    __nv_bfloat16* AsL = (__nv_bfloat16*)(sm + 5120);
    __nv_bfloat16* BsH = (__nv_bfloat16*)(sm + 10240);
    __nv_bfloat16* BsL = (__nv_bfloat16*)(sm + 27136);
    float*         sg  = (float*)(sm);                 // 64x260 fp32, post-sync overlay
    constexpr int LDA = 40, LDB = 264, LDS_G = 260;

    const int tid = threadIdx.x, lane = tid & 31, w = tid >> 5;
    const int wm = w >> 2, wn = w & 3;                 // warp tile 32x64
    const int tm = tile >> 3, tn = tile & 7;
    const int m0 = tm * 64, n0 = tn * 256;
    const int arow = tid >> 2, akq = (tid & 3) * 4;
    const int lr = lane & 15, lc = (lane >> 4) * 8;

    float acc[2][8][4];
    #pragma unroll
    for (int i = 0; i < 2; i++) for (int nb = 0; nb < 8; nb++) for (int e = 0; e < 4; e++)
        acc[i][nb][e] = 0.0f;

    for (int kt = 0; kt < KC; kt += 32) {
        float4 a1 = loadGatesA(m0 + arow, kt + akq,      t, Mm);
        float4 a2 = loadGatesA(m0 + arow, kt + akq + 16, t, Mm);
        uint4 bqh[4], bql[4];
        #pragma unroll
        for (int q = 0; q < 4; q++) {
            int cidx = q * 256 + tid;
            int row = cidx >> 5, col = (cidx & 31) * 8;
            size_t gi = (size_t)(kt + row) * G4 + n0 + col;
            bqh[q] = *(const uint4*)(g_WcatH + gi);
            bql[q] = *(const uint4*)(g_WcatL + gi);
        }
        __syncthreads();
        splitA_store(&AsH[arow * LDA + akq],      &AsL[arow * LDA + akq],      a1);
        splitA_store(&AsH[arow * LDA + akq + 16], &AsL[arow * LDA + akq + 16], a2);
        #pragma unroll
        for (int q = 0; q < 4; q++) {
            int cidx = q * 256 + tid;
            int row = cidx >> 5, col = (cidx & 31) * 8;
            *(uint4*)&BsH[row * LDB + col] = bqh[q];
            *(uint4*)&BsL[row * LDB + col] = bql[q];
        }
        __syncthreads();
        #pragma unroll
        for (int kk = 0; kk < 32; kk += 16) {
            uint32_t ah[2][4], al[2][4];
            #pragma unroll
            for (int i = 0; i < 2; i++) {
                const int rowb = wm * 32 + i * 16 + lr;
                ldmA(ah[i], &AsH[rowb * LDA + kk + lc]);
                ldmA(al[i], &AsL[rowb * LDA + kk + lc]);
            }
            uint32_t bhf[8][2], blf[8][2];
            #pragma unroll
            for (int g = 0; g < 4; g++) {
                uint32_t r4[4];
                const int coff = wn * 64 + g * 16 + lc;
                ldmBT(r4, &BsH[(kk + lr) * LDB + coff]);
                bhf[2*g][0] = r4[0]; bhf[2*g][1] = r4[1];
                bhf[2*g+1][0] = r4[2]; bhf[2*g+1][1] = r4[3];
                ldmBT(r4, &BsL[(kk + lr) * LDB + coff]);
                blf[2*g][0] = r4[0]; blf[2*g][1] = r4[1];
                blf[2*g+1][0] = r4[2]; blf[2*g+1][1] = r4[3];
            }
            #pragma unroll
            for (int i = 0; i < 2; i++)
                #pragma unroll
                for (int nb = 0; nb < 8; nb++) {
                    mma16816(acc[i][nb], ah[i], bhf[nb]);
                    mma16816(acc[i][nb], al[i], bhf[nb]);
                    mma16816(acc[i][nb], ah[i], blf[nb]);
                }
        }
    }

    __syncthreads();   // Bs dead; overlay sg
    #pragma unroll
    for (int i = 0; i < 2; i++)
        #pragma unroll
        for (int nb = 0; nb < 8; nb++) {
            const int rl0 = wm * 32 + i * 16 + (lane >> 2);
            const int cl0 = wn * 64 + nb * 8 + (lane & 3) * 2;
            #pragma unroll
            for (int e = 0; e < 4; e++) {
                const int rl = rl0 + (e >> 1) * 8;
                const int cl = cl0 + (e & 1);
                sg[rl * LDS_G + cl] = acc[i][nb][e] + g_bcat[n0 + cl];
            }
        }
    __syncthreads();

    // fused LSTM update: this tile owns rows [m0,m0+64) x j in [tn*64, tn*64+64)
    for (int idx = tid; idx < 64 * 64; idx += 256) {
        const int rl = idx >> 6, jj = idx & 63;
        const float* gb = sg + rl * LDS_G + jj * 4;
        float ig = sigm(gb[0]);
        float fg = sigm(gb[1]);
        float gg = tanhf(gb[2]);
        float og = sigm(gb[3]);
        size_t hi = (size_t)(m0 + rl) * HH + tn * 64 + jj;
        float c = fg * g_c[hi] + ig * gg;
        g_c[hi] = c;
        g_h[hi] = og * tanhf(c);
    }
}

__global__ __launch_bounds__(256, 1)
void k_scan(const float* __restrict__ X, const float* __restrict__ Mm,
            const float* __restrict__ bh_, const float* __restrict__ bf_,
            float* __restrict__ outp)
{
    extern __shared__ __align__(16) char sm[];
    #pragma unroll 1
    for (int t = 0; t < TT; t++) {
        #pragma unroll 1
        for (int tile = blockIdx.x; tile < 32; tile += GRID)
            phaseA(tile, t, X, Mm, bh_, bf_, outp, sm);
        gbar();
        #pragma unroll 1
        for (int tile = blockIdx.x; tile < 128; tile += GRID)
            phaseB(tile, t, Mm, sm);
        gbar();
    }
}

__global__ void k_hT(float* __restrict__ outp)
{
    int i = blockIdx.x * blockDim.x + threadIdx.x;
    if (i < BB * HH) outp[OFF_HT + i] = g_h[i];
}

// ---------------- launch ----------------
extern "C" void kernel_launch(void* const* d_in, const int* in_sizes, int n_in,
                              void* d_out, int out_size)
{
    const float* X      = (const float*)d_in[0];
    const float* Mm     = (const float*)d_in[1];
    const float* D      = (const float*)d_in[2];
    const float* W_gh   = (const float*)d_in[3];
    const float* b_gh   = (const float*)d_in[4];
    const float* W_gx   = (const float*)d_in[5];
    const float* b_gx   = (const float*)d_in[6];
    const float* W_hist = (const float*)d_in[7];
    const float* b_hist = (const float*)d_in[8];
    const float* W_feat = (const float*)d_in[9];
    const float* b_feat = (const float*)d_in[10];
    const float* W_comb = (const float*)d_in[11];
    const float* b_comb = (const float*)d_in[12];
    const float* W_ih   = (const float*)d_in[13];
    const float* W_hh   = (const float*)d_in[14];
    const float* b_ih   = (const float*)d_in[15];
    const float* b_hh   = (const float*)d_in[16];
    float* outp = (float*)d_out;

    static bool attr_set = false;
    if (!attr_set) {
        cudaFuncSetAttribute(k_scan, cudaFuncAttributeMaxDynamicSharedMemorySize, SMEM_BYTES);
        attr_set = true;
    }

    // Parallel precompute (carry-independent)
    k_prep<<<4096, 256>>>(D, W_gx, b_gx, W_feat, W_ih, W_hh, b_ih, b_hh,
                          W_gh, W_comb, W_hist);
    k_mma<M_GH>   <<<dim3(BTn / 64, HH / 128), 256>>>(Mm, D, b_gh);
    k_mma<M_ALPHA><<<dim3(BTn / 64, 1),        256>>>(Mm, D, b_comb);

    // Whole 128-step scan in a single persistent kernel
    k_scan<<<GRID, 256, SMEM_BYTES>>>(X, Mm, b_hist, b_feat, outp);

    k_hT<<<(BB * HH) / 256, 256>>>(outp);
}